// round 14
// baseline (speedup 1.0000x reference)
#include <cuda_runtime.h>
#include <cuda_fp16.h>
#include <math.h>

#define NN 50000
#define EE 800000
#define NF 128
#define NH 64
#define NC 40

// ---- scratch (static device globals; no allocation in kernel_launch) ----
__device__ __half  g_xh[NN * NF];    // fp16 copy of M*x
__device__ __half  g_Ah[NN * NF];    // spmm0 out (AM folded); later reused as H1 (NN x 64)
__device__ __half  g_H0h[NN * NF];   // relu(A@W0+b0)
__device__ __half  g_G1h[NN * NH];   // M * (H0@W1)  (gathered by spmm64)
__device__ __half  g_G2h[NN * NC];   // H1@W2        (gathered by spmm40)
__device__ int     g_hist[NN];
__device__ int     g_rowptr[NN + 1];
__device__ int     g_cursor[NN];
__device__ __align__(16) uint2 g_e8[EE];   // {col_u16 | v_f16<<16,  half2(adjZ,adjZ)}

__device__ __forceinline__ __half2 u2h2(unsigned u) { return *(__half2*)&u; }

// ---- PDL helpers ----
__device__ __forceinline__ void pdl_wait() {
#if __CUDA_ARCH__ >= 900
    cudaGridDependencySynchronize();
#endif
}
__device__ __forceinline__ void pdl_go() {
#if __CUDA_ARCH__ >= 900
    cudaTriggerProgrammaticLaunchCompletion();
#endif
}

// ---------------- combo: hist (atomic) + (M*x)->fp16 convert (plain launch) ----------------
#define HIST_BLOCKS ((EE + 255) / 256)
#define CVT_BLOCKS  ((NN * NF / 2 + 255) / 256)
__global__ void hist_tohalf_kernel(const int* __restrict__ row, const float* __restrict__ x,
                                   const float* __restrict__ M) {
    int b = blockIdx.x;
    if (b < HIST_BLOCKS) {
        int e = b * 256 + threadIdx.x;
        if (e < EE) atomicAdd(&g_hist[row[e]], 1);
    } else {
        int i = (b - HIST_BLOCKS) * 256 + threadIdx.x;
        if (i < NN * NF / 2) {
            float2 v = ((const float2*)x)[i];
            float m = __ldg(&M[i >> 6]);          // 64 float2 per node row
            ((__half2*)g_xh)[i] = __float22half2_rn(make_float2(v.x * m, v.y * m));
        }
    }
}

// ---------------- single-block exclusive scan ----------------
__global__ void scan_kernel() {
    pdl_wait();
    pdl_go();
    __shared__ int ssum[1024];
    const int CH = (NN + 1023) / 1024;   // 49
    int t = threadIdx.x;
    int base = t * CH;
    int local = 0;
    for (int i = 0; i < CH; i++) {
        int idx = base + i;
        if (idx < NN) local += g_hist[idx];
    }
    ssum[t] = local;
    __syncthreads();
    for (int off = 1; off < 1024; off <<= 1) {
        int v = (t >= off) ? ssum[t - off] : 0;
        __syncthreads();
        ssum[t] += v;
        __syncthreads();
    }
    int run = ssum[t] - local;
    for (int i = 0; i < CH; i++) {
        int idx = base + i;
        if (idx < NN) {
            g_rowptr[idx] = run;
            g_cursor[idx] = run;
            run += g_hist[idx];
        }
    }
    if (t == 0) g_rowptr[NN] = EE;
}

// ---- scatter: input loads in PDL prologue (overlap with scan); then atomics+stores ----
__global__ void scatter_kernel(const int* __restrict__ row, const int* __restrict__ col,
                               const float* __restrict__ adj, const float* __restrict__ adjZ) {
    const int HALF = EE / 2;
    int t = blockIdx.x * blockDim.x + threadIdx.x;
    if (t >= HALF) { pdl_wait(); return; }
    int e0 = t, e1 = t + HALF;
    // prologue: pure-input loads + packing, overlaps predecessor
    int c0 = col[e0], c1 = col[e1];
    int r0 = row[e0], r1 = row[e1];
    float a0 = adj[e0], a1 = adj[e1];
    float z0 = adjZ[e0], z1 = adjZ[e1];
    unsigned lo0 = (unsigned)(unsigned short)c0 |
                   ((unsigned)__half_as_ushort(__float2half_rn(a0)) << 16);
    unsigned lo1 = (unsigned)(unsigned short)c1 |
                   ((unsigned)__half_as_ushort(__float2half_rn(a1)) << 16);
    __half2 z20 = __half2half2(__float2half_rn(z0));
    __half2 z21 = __half2half2(__float2half_rn(z1));
    pdl_wait();   // g_cursor ready (scan complete)
    pdl_go();
    int p0 = atomicAdd(&g_cursor[r0], 1);
    int p1 = atomicAdd(&g_cursor[r1], 1);
    g_e8[p0] = make_uint2(lo0, *(unsigned*)&z20);
    g_e8[p1] = make_uint2(lo1, *(unsigned*)&z21);
}

// ---------------- SPMM 128-feat: HALF-WARP per row, LDG.128 gathers, HFMA2 ----------------
__global__ void spmm128h_kernel(const __half* __restrict__ Xh, const float* __restrict__ AM,
                                __half* __restrict__ out) {
    pdl_wait();
    pdl_go();
    int tid = threadIdx.x;
    int r = blockIdx.x * 16 + (tid >> 4);    // 16 half-warps/block
    if (r >= NN) return;
    int lane16 = tid & 15;
    int s = g_rowptr[r];
    int e = g_rowptr[r + 1];
    const uint4* X = (const uint4*)Xh;       // 16 uint4 (8 halves) per row

    float acc[8];
#pragma unroll
    for (int j = 0; j < 8; j++) acc[j] = 0.f;
    const __half2 hz = __float2half2_rn(0.f);
    int i = s;
    if ((i & 1) && i < e) {
        uint2 e0 = __ldg(&g_e8[i]);
        uint4 xv = __ldg(&X[(e0.x & 0xFFFFu) * 16 + lane16]);
        float w = __low2float(u2h2(e0.y));
        const unsigned* xc = &xv.x;
#pragma unroll
        for (int j = 0; j < 4; j++) {
            float2 f = __half22float2(u2h2(xc[j]));
            acc[2 * j] += w * f.x; acc[2 * j + 1] += w * f.y;
        }
        i++;
    }
#pragma unroll 1
    for (; i + 4 <= e; i += 4) {
        uint4 p0 = __ldg((const uint4*)&g_e8[i]);       // edges i, i+1
        uint4 p1 = __ldg((const uint4*)&g_e8[i + 2]);   // edges i+2, i+3
        uint4 x0 = __ldg(&X[(p0.x & 0xFFFFu) * 16 + lane16]);
        uint4 x1 = __ldg(&X[(p0.z & 0xFFFFu) * 16 + lane16]);
        uint4 x2 = __ldg(&X[(p1.x & 0xFFFFu) * 16 + lane16]);
        uint4 x3 = __ldg(&X[(p1.z & 0xFFFFu) * 16 + lane16]);
        __half2 w0 = u2h2(p0.y), w1 = u2h2(p0.w), w2 = u2h2(p1.y), w3 = u2h2(p1.w);
        const unsigned *c0 = &x0.x, *c1 = &x1.x, *c2 = &x2.x, *c3 = &x3.x;
#pragma unroll
        for (int j = 0; j < 4; j++) {
            __half2 a = __hfma2(w0, u2h2(c0[j]), hz);   // chain A: edges 0,2
            __half2 b = __hfma2(w1, u2h2(c1[j]), hz);   // chain B: edges 1,3
            a = __hfma2(w2, u2h2(c2[j]), a);
            b = __hfma2(w3, u2h2(c3[j]), b);
            float2 f = __half22float2(__hadd2(a, b));
            acc[2 * j] += f.x; acc[2 * j + 1] += f.y;
        }
    }
    for (; i < e; i++) {
        uint2 e0 = __ldg(&g_e8[i]);
        uint4 xv = __ldg(&X[(e0.x & 0xFFFFu) * 16 + lane16]);
        float w = __low2float(u2h2(e0.y));
        const unsigned* xc = &xv.x;
#pragma unroll
        for (int j = 0; j < 4; j++) {
            float2 f = __half22float2(u2h2(xc[j]));
            acc[2 * j] += w * f.x; acc[2 * j + 1] += w * f.y;
        }
    }
    float am = __ldg(&AM[r]);
    uint4 o;
    unsigned* oc = &o.x;
#pragma unroll
    for (int j = 0; j < 4; j++) {
        __half2 h = __float22half2_rn(make_float2(acc[2 * j] * am, acc[2 * j + 1] * am));
        oc[j] = *(unsigned*)&h;
    }
    ((uint4*)out)[r * 16 + lane16] = o;
}

// ---------------- ldmatrix helpers ----------------
__device__ __forceinline__ void ldsm_x4(unsigned& r0, unsigned& r1, unsigned& r2, unsigned& r3,
                                        unsigned addr) {
    asm volatile("ldmatrix.sync.aligned.m8n8.x4.shared.b16 {%0,%1,%2,%3}, [%4];"
                 : "=r"(r0), "=r"(r1), "=r"(r2), "=r"(r3) : "r"(addr));
}
__device__ __forceinline__ void ldsm_x2_trans(unsigned& r0, unsigned& r1, unsigned addr) {
    asm volatile("ldmatrix.sync.aligned.m8n8.x2.trans.shared.b16 {%0,%1}, [%2];"
                 : "=r"(r0), "=r"(r1) : "r"(addr));
}

// ---------------- fp16 tensor-core GEMM (mma.sync m16n8k16, fp32 accum) ----------------
// EPI 1: bias+relu fp16 out; EPI 2: plain fp16 out; EPI 3: row-scale by aux[r], fp16 out.
template <int KIN, int NOUT, int WARPN, int EPI>
__global__ __launch_bounds__(256) void gemm_f16_kernel(
        const __half* __restrict__ A, const float* __restrict__ W,
        const float* __restrict__ aux, __half* __restrict__ out) {
    constexpr int BM  = 128;
    constexpr int BK  = 16;
    constexpr int AS  = 24;
    constexpr int WS  = (NOUT == 40) ? 56 : NOUT + 8;
    constexpr int NMW = 8 / WARPN;
    constexpr int MF  = BM / (16 * NMW);
    constexpr int WN  = NOUT / WARPN;
    constexpr int NFR = WN / 8;

    __shared__ __align__(16) __half As[BM * AS];
    __shared__ __align__(16) __half Ws[BK * WS];   // row-major [k][n]
    __shared__ float biass[NOUT];

    int tid    = threadIdx.x;
    int lane   = tid & 31;
    int wid    = tid >> 5;
    int warp_m = wid % NMW;
    int warp_n = wid / NMW;
    int br     = blockIdx.x * BM;
    int qr     = lane >> 2;
    int qc     = lane & 3;

    if (EPI == 1 && tid < NOUT) biass[tid] = aux[tid];  // input, safe pre-wait

    pdl_wait();
    pdl_go();

    unsigned as_base = (unsigned)__cvta_generic_to_shared(As);
    unsigned ws_base = (unsigned)__cvta_generic_to_shared(Ws);
    int a_row  = (lane & 15);
    int a_colh = (lane >> 4) << 3;
    int b_row  = (lane & 15);

    float acc[MF][NFR][4];
#pragma unroll
    for (int i = 0; i < MF; i++)
#pragma unroll
        for (int j = 0; j < NFR; j++)
#pragma unroll
            for (int k = 0; k < 4; k++) acc[i][j][k] = 0.f;

    for (int kk = 0; kk < KIN; kk += BK) {
#pragma unroll
        for (int it = 0; it < 2; it++) {
            int i  = tid + it * 256;
            int m  = i >> 2;
            int c4 = (i & 3) * 4;
            int gr = br + m;
            uint2 v = make_uint2(0u, 0u);
            if (gr < NN) v = *(const uint2*)&A[gr * KIN + kk + c4];
            *(uint2*)&As[m * AS + c4] = v;
        }
#pragma unroll
        for (int i = tid; i < BK * NOUT / 4; i += 256) {
            int k  = i / (NOUT / 4);
            int n4 = (i % (NOUT / 4)) * 4;
            float4 v = *(const float4*)&W[(kk + k) * NOUT + n4];
            __half2 h0 = __float22half2_rn(make_float2(v.x, v.y));
            __half2 h1 = __float22half2_rn(make_float2(v.z, v.w));
            *(uint2*)&Ws[k * WS + n4] = make_uint2(*(unsigned*)&h0, *(unsigned*)&h1);
        }
        __syncthreads();

        unsigned b[NFR][2];
#pragma unroll
        for (int nf = 0; nf < NFR; nf++) {
            int n0 = warp_n * WN + nf * 8;
            ldsm_x2_trans(b[nf][0], b[nf][1],
                          ws_base + (unsigned)((b_row * WS + n0) * 2));
        }
#pragma unroll
        for (int mf = 0; mf < MF; mf++) {
            int m0 = warp_m * (16 * MF) + mf * 16;
            unsigned a0, a1, a2, a3;
            ldsm_x4(a0, a1, a2, a3,
                    as_base + (unsigned)(((m0 + a_row) * AS + a_colh) * 2));
#pragma unroll
            for (int nf = 0; nf < NFR; nf++) {
                asm("mma.sync.aligned.m16n8k16.row.col.f32.f16.f16.f32 "
                    "{%0,%1,%2,%3}, {%4,%5,%6,%7}, {%8,%9}, {%0,%1,%2,%3};"
                    : "+f"(acc[mf][nf][0]), "+f"(acc[mf][nf][1]),
                      "+f"(acc[mf][nf][2]), "+f"(acc[mf][nf][3])
                    : "r"(a0), "r"(a1), "r"(a2), "r"(a3),
                      "r"(b[nf][0]), "r"(b[nf][1]));
            }
        }
        __syncthreads();
    }

#pragma unroll
    for (int mf = 0; mf < MF; mf++) {
        int r0 = br + warp_m * (16 * MF) + mf * 16 + qr;
        int r1 = r0 + 8;
        float s0 = 1.f, s1 = 1.f;
        if (EPI == 3) {
            if (r0 < NN) s0 = __ldg(&aux[r0]);
            if (r1 < NN) s1 = __ldg(&aux[r1]);
        }
#pragma unroll
        for (int nf = 0; nf < NFR; nf++) {
            int c = warp_n * WN + nf * 8 + 2 * qc;
            float v0 = acc[mf][nf][0], v1 = acc[mf][nf][1];
            float v2 = acc[mf][nf][2], v3 = acc[mf][nf][3];
            if (EPI == 1) {
                float bx = biass[c], by = biass[c + 1];
                v0 = fmaxf(v0 + bx, 0.f); v1 = fmaxf(v1 + by, 0.f);
                v2 = fmaxf(v2 + bx, 0.f); v3 = fmaxf(v3 + by, 0.f);
            } else if (EPI == 3) {
                v0 *= s0; v1 *= s0; v2 *= s1; v3 *= s1;
            }
            if (r0 < NN) *(__half2*)&out[r0 * NOUT + c] = __float22half2_rn(make_float2(v0, v1));
            if (r1 < NN) *(__half2*)&out[r1 * NOUT + c] = __float22half2_rn(make_float2(v2, v3));
        }
    }
}

// ---- layer 1 spmm: HALF-WARP per row, H1 = relu(spmm64(adjZ, G1')*AM + b1) ----
__global__ void spmm64_kernel(const __half* __restrict__ G1h, const float* __restrict__ AM,
                              const float* __restrict__ b1, __half* __restrict__ H1h) {
    pdl_wait();
    pdl_go();
    int tid = threadIdx.x;
    int r = blockIdx.x * 16 + (tid >> 4);
    if (r >= NN) return;
    int lane16 = tid & 15;
    int s = g_rowptr[r];
    int e = g_rowptr[r + 1];
    const uint2* X = (const uint2*)G1h;   // 16 uint2 (4 halves) per row

    float acc[4];
#pragma unroll
    for (int j = 0; j < 4; j++) acc[j] = 0.f;
    const __half2 hz = __float2half2_rn(0.f);
    int i = s;
    if ((i & 1) && i < e) {
        uint2 e0 = __ldg(&g_e8[i]);
        uint2 xv = __ldg(&X[(e0.x & 0xFFFFu) * 16 + lane16]);
        float w = __low2float(u2h2(e0.y));
        float2 f0 = __half22float2(u2h2(xv.x));
        float2 f1 = __half22float2(u2h2(xv.y));
        acc[0] += w * f0.x; acc[1] += w * f0.y; acc[2] += w * f1.x; acc[3] += w * f1.y;
        i++;
    }
#pragma unroll 1
    for (; i + 4 <= e; i += 4) {
        uint4 p0 = __ldg((const uint4*)&g_e8[i]);
        uint4 p1 = __ldg((const uint4*)&g_e8[i + 2]);
        uint2 x0 = __ldg(&X[(p0.x & 0xFFFFu) * 16 + lane16]);
        uint2 x1 = __ldg(&X[(p0.z & 0xFFFFu) * 16 + lane16]);
        uint2 x2 = __ldg(&X[(p1.x & 0xFFFFu) * 16 + lane16]);
        uint2 x3 = __ldg(&X[(p1.z & 0xFFFFu) * 16 + lane16]);
        __half2 w0 = u2h2(p0.y), w1 = u2h2(p0.w), w2 = u2h2(p1.y), w3 = u2h2(p1.w);
        __half2 a0 = __hfma2(w0, u2h2(x0.x), hz);
        __half2 a1 = __hfma2(w0, u2h2(x0.y), hz);
        __half2 b0 = __hfma2(w1, u2h2(x1.x), hz);
        __half2 b1h = __hfma2(w1, u2h2(x1.y), hz);
        a0 = __hfma2(w2, u2h2(x2.x), a0);
        a1 = __hfma2(w2, u2h2(x2.y), a1);
        b0 = __hfma2(w3, u2h2(x3.x), b0);
        b1h = __hfma2(w3, u2h2(x3.y), b1h);
        float2 f0 = __half22float2(__hadd2(a0, b0));
        float2 f1 = __half22float2(__hadd2(a1, b1h));
        acc[0] += f0.x; acc[1] += f0.y; acc[2] += f1.x; acc[3] += f1.y;
    }
    for (; i < e; i++) {
        uint2 e0 = __ldg(&g_e8[i]);
        uint2 xv = __ldg(&X[(e0.x & 0xFFFFu) * 16 + lane16]);
        float w = __low2float(u2h2(e0.y));
        float2 f0 = __half22float2(u2h2(xv.x));
        float2 f1 = __half22float2(u2h2(xv.y));
        acc[0] += w * f0.x; acc[1] += w * f0.y; acc[2] += w * f1.x; acc[3] += w * f1.y;
    }

    float am = __ldg(&AM[r]);
    float4 b = __ldg(&((const float4*)b1)[lane16]);
    __half2 h0 = __float22half2_rn(make_float2(fmaxf(acc[0] * am + b.x, 0.f),
                                               fmaxf(acc[1] * am + b.y, 0.f)));
    __half2 h1 = __float22half2_rn(make_float2(fmaxf(acc[2] * am + b.z, 0.f),
                                               fmaxf(acc[3] * am + b.w, 0.f)));
    ((uint2*)H1h)[r * 16 + lane16] = make_uint2(*(unsigned*)&h0, *(unsigned*)&h1);
}

// ---- layer 2 fused: out = log_softmax(spmm40(v, G2h) + b2), one warp/row ----
__global__ void spmm40_final_kernel(const __half* __restrict__ G2h, const float* __restrict__ b2,
                                    float* __restrict__ out) {
    pdl_wait();
    int tid = threadIdx.x;
    int r = blockIdx.x * (blockDim.x >> 5) + (tid >> 5);
    if (r >= NN) return;
    int lane = tid & 31;
    bool act = lane < 20;
    int s = g_rowptr[r];
    int e = g_rowptr[r + 1];
    const __half2* X = (const __half2*)G2h;
    int li = act ? lane : 0;

    float2 acc = make_float2(0.f, 0.f);
    const __half2 hz = __float2half2_rn(0.f);
    int i = s;
    if ((i & 1) && i < e) {
        uint2 e0 = __ldg(&g_e8[i]);
        float2 x0 = __half22float2(__ldg(&X[(e0.x & 0xFFFFu) * 20 + li]));
        float w = __half2float(__ushort_as_half((unsigned short)(e0.x >> 16)));
        acc.x += w * x0.x; acc.y += w * x0.y;
        i++;
    }
#pragma unroll 1
    for (; i + 8 <= e; i += 8) {
        uint4 p0 = __ldg((const uint4*)&g_e8[i]);
        uint4 p1 = __ldg((const uint4*)&g_e8[i + 2]);
        uint4 p2 = __ldg((const uint4*)&g_e8[i + 4]);
        uint4 p3 = __ldg((const uint4*)&g_e8[i + 6]);
        __half2 x0 = __ldg(&X[(p0.x & 0xFFFFu) * 20 + li]);
        __half2 x1 = __ldg(&X[(p0.z & 0xFFFFu) * 20 + li]);
        __half2 x2 = __ldg(&X[(p1.x & 0xFFFFu) * 20 + li]);
        __half2 x3 = __ldg(&X[(p1.z & 0xFFFFu) * 20 + li]);
        __half2 x4 = __ldg(&X[(p2.x & 0xFFFFu) * 20 + li]);
        __half2 x5 = __ldg(&X[(p2.z & 0xFFFFu) * 20 + li]);
        __half2 x6 = __ldg(&X[(p3.x & 0xFFFFu) * 20 + li]);
        __half2 x7 = __ldg(&X[(p3.z & 0xFFFFu) * 20 + li]);
        __half2 v0 = __half2half2(__ushort_as_half((unsigned short)(p0.x >> 16)));
        __half2 v1 = __half2half2(__ushort_as_half((unsigned short)(p0.z >> 16)));
        __half2 v2 = __half2half2(__ushort_as_half((unsigned short)(p1.x >> 16)));
        __half2 v3 = __half2half2(__ushort_as_half((unsigned short)(p1.z >> 16)));
        __half2 v4 = __half2half2(__ushort_as_half((unsigned short)(p2.x >> 16)));
        __half2 v5 = __half2half2(__ushort_as_half((unsigned short)(p2.z >> 16)));
        __half2 v6 = __half2half2(__ushort_as_half((unsigned short)(p3.x >> 16)));
        __half2 v7 = __half2half2(__ushort_as_half((unsigned short)(p3.z >> 16)));
        __half2 a0 = __hfma2(v0, x0, hz);
        __half2 a1 = __hfma2(v1, x1, hz);
        __half2 a2 = __hfma2(v2, x2, hz);
        __half2 a3 = __hfma2(v3, x3, hz);
        a0 = __hfma2(v4, x4, a0);
        a1 = __hfma2(v5, x5, a1);
        a2 = __hfma2(v6, x6, a2);
        a3 = __hfma2(v7, x7, a3);
        float2 f = __half22float2(__hadd2(__hadd2(a0, a1), __hadd2(a2, a3)));
        acc.x += f.x; acc.y += f.y;
    }
    for (; i < e; i++) {
        uint2 e0 = __ldg(&g_e8[i]);
        float2 x0 = __half22float2(__ldg(&X[(e0.x & 0xFFFFu) * 20 + li]));
        float w = __half2float(__ushort_as_half((unsigned short)(e0.x >> 16)));
        acc.x += w * x0.x; acc.y += w * x0.y;
    }

    float v0 = 0.f, v1 = 0.f;
    if (act) {
        float2 b = __ldg(&((const float2*)b2)[lane]);
        v0 = acc.x + b.x;
        v1 = acc.y + b.y;
    }

    float m = act ? fmaxf(v0, v1) : -INFINITY;
#pragma unroll
    for (int o = 16; o > 0; o >>= 1) m = fmaxf(m, __shfl_xor_sync(0xffffffffu, m, o));
    float sum = act ? (expf(v0 - m) + expf(v1 - m)) : 0.f;
#pragma unroll
    for (int o = 16; o > 0; o >>= 1) sum += __shfl_xor_sync(0xffffffffu, sum, o);
    float lse = m + logf(sum);

    if (act) {
        ((float2*)out)[r * 20 + lane] = make_float2(v0 - lse, v1 - lse);
    }
}

// ---------------- launch ----------------
static inline cudaLaunchConfig_t pdl_cfg(int grid, int block) {
    cudaLaunchConfig_t cfg = {};
    cfg.gridDim  = dim3(grid, 1, 1);
    cfg.blockDim = dim3(block, 1, 1);
    static cudaLaunchAttribute attr[1];
    attr[0].id = cudaLaunchAttributeProgrammaticStreamSerialization;
    attr[0].val.programmaticStreamSerializationAllowed = 1;
    cfg.attrs = attr;
    cfg.numAttrs = 1;
    return cfg;
}

extern "C" void kernel_launch(void* const* d_in, const int* in_sizes, int n_in,
                              void* d_out, int out_size) {
    const float* x    = (const float*)d_in[0];
    const float* M    = (const float*)d_in[1];
    const float* AM   = (const float*)d_in[2];
    const float* adj  = (const float*)d_in[3];
    const float* adjZ = (const float*)d_in[4];
    const float* W0   = (const float*)d_in[5];
    const float* b0   = (const float*)d_in[6];
    const float* W1   = (const float*)d_in[7];
    const float* b1   = (const float*)d_in[8];
    const float* W2   = (const float*)d_in[9];
    const float* b2   = (const float*)d_in[10];
    const int*   row  = (const int*)d_in[11];
    const int*   col  = (const int*)d_in[12];
    float* out = (float*)d_out;

    void *pXh, *pAh, *pH0h, *pG1h, *pG2h, *pHist;
    cudaGetSymbolAddress(&pXh,  g_xh);
    cudaGetSymbolAddress(&pAh,  g_Ah);
    cudaGetSymbolAddress(&pH0h, g_H0h);
    cudaGetSymbolAddress(&pG1h, g_G1h);
    cudaGetSymbolAddress(&pG2h, g_G2h);
    cudaGetSymbolAddress(&pHist, g_hist);

    // CSR build + (M*x)->fp16 conversion
    cudaMemsetAsync(pHist, 0, NN * sizeof(int));
    hist_tohalf_kernel<<<HIST_BLOCKS + CVT_BLOCKS, 256>>>(row, x, M);   // plain (after memset)

    {
        cudaLaunchConfig_t c = pdl_cfg(1, 1024);
        cudaLaunchKernelEx(&c, scan_kernel);
    }
    {
        cudaLaunchConfig_t c = pdl_cfg((EE / 2 + 255) / 256, 256);
        cudaLaunchKernelEx(&c, scatter_kernel, row, col, adj, adjZ);
    }

    const int spmmHW = (NN + 15) / 16;          // half-warp per row, 16 rows/block
    const int spmmW  = (NN + 7) / 8;            // warp per row (spmm40)
    const int gemmBlocks = (NN + 127) / 128;    // BM=128

    // layer 0
    {
        cudaLaunchConfig_t c = pdl_cfg(spmmHW, 256);
        cudaLaunchKernelEx(&c, spmm128h_kernel, (const __half*)pXh, AM, (__half*)pAh);
    }
    {
        cudaLaunchConfig_t c = pdl_cfg(gemmBlocks, 256);
        cudaLaunchKernelEx(&c, gemm_f16_kernel<128, 128, 2, 1>,
                           (const __half*)pAh, W0, b0, (__half*)pH0h);
    }
    // layer 1 (commuted)
    {
        cudaLaunchConfig_t c = pdl_cfg(gemmBlocks, 256);
        cudaLaunchKernelEx(&c, gemm_f16_kernel<128, 64, 2, 3>,
                           (const __half*)pH0h, W1, M, (__half*)pG1h);
    }
    {
        cudaLaunchConfig_t c = pdl_cfg(spmmHW, 256);
        cudaLaunchKernelEx(&c, spmm64_kernel, (const __half*)pG1h, AM, b1, (__half*)pAh);
    }
    // layer 2 (commuted)
    {
        cudaLaunchConfig_t c = pdl_cfg(gemmBlocks, 256);
        cudaLaunchKernelEx(&c, gemm_f16_kernel<64, 40, 1, 2>,
                           (const __half*)pAh, W2, nullptr, (__half*)pG2h);
    }
    {
        cudaLaunchConfig_t c = pdl_cfg(spmmW, 256);
        cudaLaunchKernelEx(&c, spmm40_final_kernel, (const __half*)pG2h, b2, out);
    }
}

// round 15
// speedup vs baseline: 1.2776x; 1.2776x over previous
#include <cuda_runtime.h>
#include <cuda_fp16.h>
#include <math.h>

#define NN 50000
#define EE 800000
#define NF 128
#define NH 64
#define NC 40

// ---- scratch (static device globals; no allocation in kernel_launch) ----
__device__ __half  g_xh[NN * NF];    // fp16 copy of M*x
__device__ __half  g_Ah[NN * NF];    // spmm0 out (AM folded); later reused as H1 (NN x 64)
__device__ __half  g_H0h[NN * NF];   // relu(A@W0+b0)
__device__ __half  g_G1h[NN * NH];   // M * (H0@W1)  (gathered by spmm64)
__device__ __half  g_G2h[NN * NC];   // H1@W2        (gathered by spmm40)
__device__ int     g_hist[NN];       // zero-init; re-zeroed by scan_kernel each run
__device__ int     g_rowptr[NN + 1];
__device__ int     g_cursor[NN];
__device__ __align__(16) uint2 g_e8[EE];   // {col_u16 | v_f16<<16,  half2(adjZ,adjZ)}

// ---------------- combo: hist (atomic) + (M*x)->fp16 convert, one launch ----------------
#define HIST_BLOCKS ((EE + 255) / 256)
#define CVT_BLOCKS  ((NN * NF / 2 + 255) / 256)
__global__ void hist_tohalf_kernel(const int* __restrict__ row, const float* __restrict__ x,
                                   const float* __restrict__ M) {
    int b = blockIdx.x;
    if (b < HIST_BLOCKS) {
        int e = b * 256 + threadIdx.x;
        if (e < EE) atomicAdd(&g_hist[row[e]], 1);
    } else {
        int i = (b - HIST_BLOCKS) * 256 + threadIdx.x;
        if (i < NN * NF / 2) {
            float2 v = ((const float2*)x)[i];
            float m = __ldg(&M[i >> 6]);          // 64 float2 per node row
            ((__half2*)g_xh)[i] = __float22half2_rn(make_float2(v.x * m, v.y * m));
        }
    }
}

// ---------------- single-block exclusive scan (also re-zeroes g_hist for next run) ----------------
__global__ void scan_kernel() {
    __shared__ int ssum[1024];
    const int CH = (NN + 1023) / 1024;   // 49
    int t = threadIdx.x;
    int base = t * CH;
    int local = 0;
    for (int i = 0; i < CH; i++) {
        int idx = base + i;
        if (idx < NN) local += g_hist[idx];
    }
    ssum[t] = local;
    __syncthreads();
    for (int off = 1; off < 1024; off <<= 1) {
        int v = (t >= off) ? ssum[t - off] : 0;
        __syncthreads();
        ssum[t] += v;
        __syncthreads();
    }
    int run = ssum[t] - local;
    for (int i = 0; i < CH; i++) {
        int idx = base + i;
        if (idx < NN) {
            g_rowptr[idx] = run;
            g_cursor[idx] = run;
            run += g_hist[idx];
            g_hist[idx] = 0;          // re-zero for next graph replay (replaces memset node)
        }
    }
    if (t == 0) g_rowptr[NN] = EE;
}

// ---- scatter: 2 edges/thread for MLP; weight stored as half2(adjZ,adjZ) ----
__global__ void scatter_kernel(const int* __restrict__ row, const int* __restrict__ col,
                               const float* __restrict__ adj, const float* __restrict__ adjZ) {
    const int HALF = EE / 2;
    int t = blockIdx.x * blockDim.x + threadIdx.x;
    if (t >= HALF) return;
    int e0 = t, e1 = t + HALF;
    int c0 = col[e0], c1 = col[e1];
    int r0 = row[e0], r1 = row[e1];
    float a0 = adj[e0], a1 = adj[e1];
    float z0 = adjZ[e0], z1 = adjZ[e1];
    int p0 = atomicAdd(&g_cursor[r0], 1);
    int p1 = atomicAdd(&g_cursor[r1], 1);
    unsigned lo0 = (unsigned)(unsigned short)c0 |
                   ((unsigned)__half_as_ushort(__float2half_rn(a0)) << 16);
    unsigned lo1 = (unsigned)(unsigned short)c1 |
                   ((unsigned)__half_as_ushort(__float2half_rn(a1)) << 16);
    __half2 z20 = __half2half2(__float2half_rn(z0));
    __half2 z21 = __half2half2(__float2half_rn(z1));
    g_e8[p0] = make_uint2(lo0, *(unsigned*)&z20);
    g_e8[p1] = make_uint2(lo1, *(unsigned*)&z21);
}

__device__ __forceinline__ __half2 u2h2(unsigned u) { return *(__half2*)&u; }

// ---------------- SPMM 128-feat (layer 0): uint4 edge loads, 4-chain HFMA2, flush/8 ----------------
__global__ void spmm128h_kernel(const __half* __restrict__ Xh, const float* __restrict__ AM,
                                __half* __restrict__ out) {
    int r = (blockIdx.x * blockDim.x + threadIdx.x) >> 5;
    if (r >= NN) return;
    int lane = threadIdx.x & 31;
    int s = g_rowptr[r];
    int e = g_rowptr[r + 1];
    const uint2* X = (const uint2*)Xh;

    float4 acc = make_float4(0.f, 0.f, 0.f, 0.f);
    const __half2 hz = __float2half2_rn(0.f);
    int i = s;
    // peel to even index so uint4 loads are 16B-aligned
    if ((i & 1) && i < e) {
        uint2 e0 = __ldg(&g_e8[i]);
        uint2 u0 = __ldg(&X[(e0.x & 0xFFFFu) * 32 + lane]);
        float w = __low2float(u2h2(e0.y));
        float2 a = __half22float2(u2h2(u0.x));
        float2 b = __half22float2(u2h2(u0.y));
        acc.x += w * a.x; acc.y += w * a.y; acc.z += w * b.x; acc.w += w * b.y;
        i++;
    }
#pragma unroll 1
    for (; i + 8 <= e; i += 8) {
        uint4 p0 = __ldg((const uint4*)&g_e8[i]);       // edges i, i+1
        uint4 p1 = __ldg((const uint4*)&g_e8[i + 2]);
        uint4 p2 = __ldg((const uint4*)&g_e8[i + 4]);
        uint4 p3 = __ldg((const uint4*)&g_e8[i + 6]);
        uint2 u0 = __ldg(&X[(p0.x & 0xFFFFu) * 32 + lane]);
        uint2 u1 = __ldg(&X[(p0.z & 0xFFFFu) * 32 + lane]);
        uint2 u2 = __ldg(&X[(p1.x & 0xFFFFu) * 32 + lane]);
        uint2 u3 = __ldg(&X[(p1.z & 0xFFFFu) * 32 + lane]);
        uint2 u4 = __ldg(&X[(p2.x & 0xFFFFu) * 32 + lane]);
        uint2 u5 = __ldg(&X[(p2.z & 0xFFFFu) * 32 + lane]);
        uint2 u6 = __ldg(&X[(p3.x & 0xFFFFu) * 32 + lane]);
        uint2 u7 = __ldg(&X[(p3.z & 0xFFFFu) * 32 + lane]);
        // 4 independent chain pairs, each 2 HFMA2 deep
        __half2 a0 = __hfma2(u2h2(p0.y), u2h2(u0.x), hz), b0 = __hfma2(u2h2(p0.y), u2h2(u0.y), hz);
        __half2 a1 = __hfma2(u2h2(p0.w), u2h2(u1.x), hz), b1 = __hfma2(u2h2(p0.w), u2h2(u1.y), hz);
        __half2 a2 = __hfma2(u2h2(p1.y), u2h2(u2.x), hz), b2 = __hfma2(u2h2(p1.y), u2h2(u2.y), hz);
        __half2 a3 = __hfma2(u2h2(p1.w), u2h2(u3.x), hz), b3 = __hfma2(u2h2(p1.w), u2h2(u3.y), hz);
        a0 = __hfma2(u2h2(p2.y), u2h2(u4.x), a0); b0 = __hfma2(u2h2(p2.y), u2h2(u4.y), b0);
        a1 = __hfma2(u2h2(p2.w), u2h2(u5.x), a1); b1 = __hfma2(u2h2(p2.w), u2h2(u5.y), b1);
        a2 = __hfma2(u2h2(p3.y), u2h2(u6.x), a2); b2 = __hfma2(u2h2(p3.y), u2h2(u6.y), b2);
        a3 = __hfma2(u2h2(p3.w), u2h2(u7.x), a3); b3 = __hfma2(u2h2(p3.w), u2h2(u7.y), b3);
        // flush to fp32
        __half2 sa = __hadd2(__hadd2(a0, a1), __hadd2(a2, a3));
        __half2 sb = __hadd2(__hadd2(b0, b1), __hadd2(b2, b3));
        float2 fa = __half22float2(sa);
        float2 fb = __half22float2(sb);
        acc.x += fa.x; acc.y += fa.y; acc.z += fb.x; acc.w += fb.y;
    }
    for (; i < e; i++) {
        uint2 e0 = __ldg(&g_e8[i]);
        uint2 u0 = __ldg(&X[(e0.x & 0xFFFFu) * 32 + lane]);
        float w = __low2float(u2h2(e0.y));
        float2 a = __half22float2(u2h2(u0.x));
        float2 b = __half22float2(u2h2(u0.y));
        acc.x += w * a.x; acc.y += w * a.y; acc.z += w * b.x; acc.w += w * b.y;
    }
    float am = __ldg(&AM[r]);
    __half2 h0 = __float22half2_rn(make_float2(acc.x * am, acc.y * am));
    __half2 h1 = __float22half2_rn(make_float2(acc.z * am, acc.w * am));
    ((uint2*)out)[r * 32 + lane] = make_uint2(*(unsigned*)&h0, *(unsigned*)&h1);
}

// ---------------- ldmatrix helpers ----------------
__device__ __forceinline__ void ldsm_x4(unsigned& r0, unsigned& r1, unsigned& r2, unsigned& r3,
                                        unsigned addr) {
    asm volatile("ldmatrix.sync.aligned.m8n8.x4.shared.b16 {%0,%1,%2,%3}, [%4];"
                 : "=r"(r0), "=r"(r1), "=r"(r2), "=r"(r3) : "r"(addr));
}
__device__ __forceinline__ void ldsm_x2_trans(unsigned& r0, unsigned& r1, unsigned addr) {
    asm volatile("ldmatrix.sync.aligned.m8n8.x2.trans.shared.b16 {%0,%1}, [%2];"
                 : "=r"(r0), "=r"(r1) : "r"(addr));
}

// ---------------- fp16 tensor-core GEMM (mma.sync m16n8k16, fp32 accum) ----------------
// EPI 1: bias+relu fp16 out; EPI 2: plain fp16 out; EPI 3: row-scale by aux[r], fp16 out.
template <int KIN, int NOUT, int WARPN, int EPI>
__global__ __launch_bounds__(256) void gemm_f16_kernel(
        const __half* __restrict__ A, const float* __restrict__ W,
        const float* __restrict__ aux, __half* __restrict__ out) {
    constexpr int BM  = 128;
    constexpr int BK  = 16;
    constexpr int AS  = 24;
    constexpr int WS  = (NOUT == 40) ? 56 : NOUT + 8;
    constexpr int NMW = 8 / WARPN;
    constexpr int MF  = BM / (16 * NMW);
    constexpr int WN  = NOUT / WARPN;
    constexpr int NFR = WN / 8;

    __shared__ __align__(16) __half As[BM * AS];
    __shared__ __align__(16) __half Ws[BK * WS];   // row-major [k][n]
    __shared__ float biass[NOUT];

    int tid    = threadIdx.x;
    int lane   = tid & 31;
    int wid    = tid >> 5;
    int warp_m = wid % NMW;
    int warp_n = wid / NMW;
    int br     = blockIdx.x * BM;
    int qr     = lane >> 2;
    int qc     = lane & 3;

    if (EPI == 1 && tid < NOUT) biass[tid] = aux[tid];

    unsigned as_base = (unsigned)__cvta_generic_to_shared(As);
    unsigned ws_base = (unsigned)__cvta_generic_to_shared(Ws);
    int a_row  = (lane & 15);
    int a_colh = (lane >> 4) << 3;
    int b_row  = (lane & 15);

    float acc[MF][NFR][4];
#pragma unroll
    for (int i = 0; i < MF; i++)
#pragma unroll
        for (int j = 0; j < NFR; j++)
#pragma unroll
            for (int k = 0; k < 4; k++) acc[i][j][k] = 0.f;

    for (int kk = 0; kk < KIN; kk += BK) {
#pragma unroll
        for (int it = 0; it < 2; it++) {
            int i  = tid + it * 256;
            int m  = i >> 2;
            int c4 = (i & 3) * 4;
            int gr = br + m;
            uint2 v = make_uint2(0u, 0u);
            if (gr < NN) v = *(const uint2*)&A[gr * KIN + kk + c4];
            *(uint2*)&As[m * AS + c4] = v;
        }
#pragma unroll
        for (int i = tid; i < BK * NOUT / 4; i += 256) {
            int k  = i / (NOUT / 4);
            int n4 = (i % (NOUT / 4)) * 4;
            float4 v = *(const float4*)&W[(kk + k) * NOUT + n4];
            __half2 h0 = __float22half2_rn(make_float2(v.x, v.y));
            __half2 h1 = __float22half2_rn(make_float2(v.z, v.w));
            *(uint2*)&Ws[k * WS + n4] = make_uint2(*(unsigned*)&h0, *(unsigned*)&h1);
        }
        __syncthreads();

        unsigned b[NFR][2];
#pragma unroll
        for (int nf = 0; nf < NFR; nf++) {
            int n0 = warp_n * WN + nf * 8;
            ldsm_x2_trans(b[nf][0], b[nf][1],
                          ws_base + (unsigned)((b_row * WS + n0) * 2));
        }
#pragma unroll
        for (int mf = 0; mf < MF; mf++) {
            int m0 = warp_m * (16 * MF) + mf * 16;
            unsigned a0, a1, a2, a3;
            ldsm_x4(a0, a1, a2, a3,
                    as_base + (unsigned)(((m0 + a_row) * AS + a_colh) * 2));
#pragma unroll
            for (int nf = 0; nf < NFR; nf++) {
                asm("mma.sync.aligned.m16n8k16.row.col.f32.f16.f16.f32 "
                    "{%0,%1,%2,%3}, {%4,%5,%6,%7}, {%8,%9}, {%0,%1,%2,%3};"
                    : "+f"(acc[mf][nf][0]), "+f"(acc[mf][nf][1]),
                      "+f"(acc[mf][nf][2]), "+f"(acc[mf][nf][3])
                    : "r"(a0), "r"(a1), "r"(a2), "r"(a3),
                      "r"(b[nf][0]), "r"(b[nf][1]));
            }
        }
        __syncthreads();
    }

#pragma unroll
    for (int mf = 0; mf < MF; mf++) {
        int r0 = br + warp_m * (16 * MF) + mf * 16 + qr;
        int r1 = r0 + 8;
        float s0 = 1.f, s1 = 1.f;
        if (EPI == 3) {
            if (r0 < NN) s0 = __ldg(&aux[r0]);
            if (r1 < NN) s1 = __ldg(&aux[r1]);
        }
#pragma unroll
        for (int nf = 0; nf < NFR; nf++) {
            int c = warp_n * WN + nf * 8 + 2 * qc;
            float v0 = acc[mf][nf][0], v1 = acc[mf][nf][1];
            float v2 = acc[mf][nf][2], v3 = acc[mf][nf][3];
            if (EPI == 1) {
                float bx = biass[c], by = biass[c + 1];
                v0 = fmaxf(v0 + bx, 0.f); v1 = fmaxf(v1 + by, 0.f);
                v2 = fmaxf(v2 + bx, 0.f); v3 = fmaxf(v3 + by, 0.f);
            } else if (EPI == 3) {
                v0 *= s0; v1 *= s0; v2 *= s1; v3 *= s1;
            }
            if (r0 < NN) *(__half2*)&out[r0 * NOUT + c] = __float22half2_rn(make_float2(v0, v1));
            if (r1 < NN) *(__half2*)&out[r1 * NOUT + c] = __float22half2_rn(make_float2(v2, v3));
        }
    }
}

// ---- layer 1 spmm: H1 = relu(spmm64(adjZ, G1')*AM + b1), uint4 edges + HFMA2 ----
__global__ void spmm64_kernel(const __half* __restrict__ G1h, const float* __restrict__ AM,
                              const float* __restrict__ b1, __half* __restrict__ H1h) {
    int tid = threadIdx.x;
    int r = blockIdx.x * (blockDim.x >> 5) + (tid >> 5);
    if (r >= NN) return;
    int lane = tid & 31;
    int s = g_rowptr[r];
    int e = g_rowptr[r + 1];
    const __half2* X = (const __half2*)G1h;   // 32 half2 per row

    float2 acc = make_float2(0.f, 0.f);
    const __half2 hz = __float2half2_rn(0.f);
    int i = s;
    if ((i & 1) && i < e) {
        uint2 e0 = __ldg(&g_e8[i]);
        float2 x0 = __half22float2(__ldg(&X[(e0.x & 0xFFFFu) * 32 + lane]));
        float w = __low2float(u2h2(e0.y));
        acc.x += w * x0.x; acc.y += w * x0.y;
        i++;
    }
#pragma unroll 1
    for (; i + 8 <= e; i += 8) {
        uint4 p0 = __ldg((const uint4*)&g_e8[i]);
        uint4 p1 = __ldg((const uint4*)&g_e8[i + 2]);
        uint4 p2 = __ldg((const uint4*)&g_e8[i + 4]);
        uint4 p3 = __ldg((const uint4*)&g_e8[i + 6]);
        __half2 x0 = __ldg(&X[(p0.x & 0xFFFFu) * 32 + lane]);
        __half2 x1 = __ldg(&X[(p0.z & 0xFFFFu) * 32 + lane]);
        __half2 x2 = __ldg(&X[(p1.x & 0xFFFFu) * 32 + lane]);
        __half2 x3 = __ldg(&X[(p1.z & 0xFFFFu) * 32 + lane]);
        __half2 x4 = __ldg(&X[(p2.x & 0xFFFFu) * 32 + lane]);
        __half2 x5 = __ldg(&X[(p2.z & 0xFFFFu) * 32 + lane]);
        __half2 x6 = __ldg(&X[(p3.x & 0xFFFFu) * 32 + lane]);
        __half2 x7 = __ldg(&X[(p3.z & 0xFFFFu) * 32 + lane]);
        __half2 a0 = __hfma2(u2h2(p0.y), x0, hz);
        __half2 a1 = __hfma2(u2h2(p0.w), x1, hz);
        __half2 a2 = __hfma2(u2h2(p1.y), x2, hz);
        __half2 a3 = __hfma2(u2h2(p1.w), x3, hz);
        a0 = __hfma2(u2h2(p2.y), x4, a0);
        a1 = __hfma2(u2h2(p2.w), x5, a1);
        a2 = __hfma2(u2h2(p3.y), x6, a2);
        a3 = __hfma2(u2h2(p3.w), x7, a3);
        float2 f = __half22float2(__hadd2(__hadd2(a0, a1), __hadd2(a2, a3)));
        acc.x += f.x; acc.y += f.y;
    }
    for (; i < e; i++) {
        uint2 e0 = __ldg(&g_e8[i]);
        float2 x0 = __half22float2(__ldg(&X[(e0.x & 0xFFFFu) * 32 + lane]));
        float w = __low2float(u2h2(e0.y));
        acc.x += w * x0.x; acc.y += w * x0.y;
    }

    float am = __ldg(&AM[r]);
    float2 b = __ldg(&((const float2*)b1)[lane]);
    float2 hv;
    hv.x = fmaxf(acc.x * am + b.x, 0.f);
    hv.y = fmaxf(acc.y * am + b.y, 0.f);
    ((__half2*)H1h)[r * 32 + lane] = __float22half2_rn(hv);
}

// ---- layer 2 fused: out = log_softmax(spmm40(v, G2h) + b2), uint4 edges + HFMA2 ----
__global__ void spmm40_final_kernel(const __half* __restrict__ G2h, const float* __restrict__ b2,
                                    float* __restrict__ out) {
    int tid = threadIdx.x;
    int r = blockIdx.x * (blockDim.x >> 5) + (tid >> 5);
    if (r >= NN) return;
    int lane = tid & 31;
    bool act = lane < 20;
    int s = g_rowptr[r];
    int e = g_rowptr[r + 1];
    const __half2* X = (const __half2*)G2h;
    int li = act ? lane : 0;

    float2 acc = make_float2(0.f, 0.f);
    const __half2 hz = __float2half2_rn(0.f);
    int i = s;
    if ((i & 1) && i < e) {
        uint2 e0 = __ldg(&g_e8[i]);
        float2 x0 = __half22float2(__ldg(&X[(e0.x & 0xFFFFu) * 20 + li]));
        float w = __half2float(__ushort_as_half((unsigned short)(e0.x >> 16)));
        acc.x += w * x0.x; acc.y += w * x0.y;
        i++;
    }
#pragma unroll 1
    for (; i + 8 <= e; i += 8) {
        uint4 p0 = __ldg((const uint4*)&g_e8[i]);
        uint4 p1 = __ldg((const uint4*)&g_e8[i + 2]);
        uint4 p2 = __ldg((const uint4*)&g_e8[i + 4]);
        uint4 p3 = __ldg((const uint4*)&g_e8[i + 6]);
        __half2 x0 = __ldg(&X[(p0.x & 0xFFFFu) * 20 + li]);
        __half2 x1 = __ldg(&X[(p0.z & 0xFFFFu) * 20 + li]);
        __half2 x2 = __ldg(&X[(p1.x & 0xFFFFu) * 20 + li]);
        __half2 x3 = __ldg(&X[(p1.z & 0xFFFFu) * 20 + li]);
        __half2 x4 = __ldg(&X[(p2.x & 0xFFFFu) * 20 + li]);
        __half2 x5 = __ldg(&X[(p2.z & 0xFFFFu) * 20 + li]);
        __half2 x6 = __ldg(&X[(p3.x & 0xFFFFu) * 20 + li]);
        __half2 x7 = __ldg(&X[(p3.z & 0xFFFFu) * 20 + li]);
        __half2 v0 = __half2half2(__ushort_as_half((unsigned short)(p0.x >> 16)));
        __half2 v1 = __half2half2(__ushort_as_half((unsigned short)(p0.z >> 16)));
        __half2 v2 = __half2half2(__ushort_as_half((unsigned short)(p1.x >> 16)));
        __half2 v3 = __half2half2(__ushort_as_half((unsigned short)(p1.z >> 16)));
        __half2 v4 = __half2half2(__ushort_as_half((unsigned short)(p2.x >> 16)));
        __half2 v5 = __half2half2(__ushort_as_half((unsigned short)(p2.z >> 16)));
        __half2 v6 = __half2half2(__ushort_as_half((unsigned short)(p3.x >> 16)));
        __half2 v7 = __half2half2(__ushort_as_half((unsigned short)(p3.z >> 16)));
        __half2 a0 = __hfma2(v0, x0, hz);
        __half2 a1 = __hfma2(v1, x1, hz);
        __half2 a2 = __hfma2(v2, x2, hz);
        __half2 a3 = __hfma2(v3, x3, hz);
        a0 = __hfma2(v4, x4, a0);
        a1 = __hfma2(v5, x5, a1);
        a2 = __hfma2(v6, x6, a2);
        a3 = __hfma2(v7, x7, a3);
        float2 f = __half22float2(__hadd2(__hadd2(a0, a1), __hadd2(a2, a3)));
        acc.x += f.x; acc.y += f.y;
    }
    for (; i < e; i++) {
        uint2 e0 = __ldg(&g_e8[i]);
        float2 x0 = __half22float2(__ldg(&X[(e0.x & 0xFFFFu) * 20 + li]));
        float w = __half2float(__ushort_as_half((unsigned short)(e0.x >> 16)));
        acc.x += w * x0.x; acc.y += w * x0.y;
    }

    float v0 = 0.f, v1 = 0.f;
    if (act) {
        float2 b = __ldg(&((const float2*)b2)[lane]);
        v0 = acc.x + b.x;
        v1 = acc.y + b.y;
    }

    float m = act ? fmaxf(v0, v1) : -INFINITY;
#pragma unroll
    for (int o = 16; o > 0; o >>= 1) m = fmaxf(m, __shfl_xor_sync(0xffffffffu, m, o));
    float sum = act ? (expf(v0 - m) + expf(v1 - m)) : 0.f;
#pragma unroll
    for (int o = 16; o > 0; o >>= 1) sum += __shfl_xor_sync(0xffffffffu, sum, o);
    float lse = m + logf(sum);

    if (act) {
        ((float2*)out)[r * 20 + lane] = make_float2(v0 - lse, v1 - lse);
    }
}

// ---------------- launch ----------------
extern "C" void kernel_launch(void* const* d_in, const int* in_sizes, int n_in,
                              void* d_out, int out_size) {
    const float* x    = (const float*)d_in[0];
    const float* M    = (const float*)d_in[1];
    const float* AM   = (const float*)d_in[2];
    const float* adj  = (const float*)d_in[3];
    const float* adjZ = (const float*)d_in[4];
    const float* W0   = (const float*)d_in[5];
    const float* b0   = (const float*)d_in[6];
    const float* W1   = (const float*)d_in[7];
    const float* b1   = (const float*)d_in[8];
    const float* W2   = (const float*)d_in[9];
    const float* b2   = (const float*)d_in[10];
    const int*   row  = (const int*)d_in[11];
    const int*   col  = (const int*)d_in[12];
    float* out = (float*)d_out;

    void *pXh, *pAh, *pH0h, *pG1h, *pG2h;
    cudaGetSymbolAddress(&pXh,  g_xh);
    cudaGetSymbolAddress(&pAh,  g_Ah);
    cudaGetSymbolAddress(&pH0h, g_H0h);
    cudaGetSymbolAddress(&pG1h, g_G1h);
    cudaGetSymbolAddress(&pG2h, g_G2h);

    // CSR build + (M*x)->fp16 conversion (g_hist re-zeroed inside scan_kernel)
    hist_tohalf_kernel<<<HIST_BLOCKS + CVT_BLOCKS, 256>>>(row, x, M);
    scan_kernel<<<1, 1024>>>();
    scatter_kernel<<<(EE / 2 + 255) / 256, 256>>>(row, col, adj, adjZ);

    const int spmmBlocks = (NN + 7) / 8;        // 8 warps/block, 1 warp/row
    const int gemmBlocks = (NN + 127) / 128;    // BM=128

    // layer 0: H0 = relu((spmm(adjZ, M*x) * AM) @ W0 + b0)
    spmm128h_kernel<<<spmmBlocks, 256>>>((const __half*)pXh, AM, (__half*)pAh);
    gemm_f16_kernel<128, 128, 2, 1><<<gemmBlocks, 256>>>((const __half*)pAh, W0, b0, (__half*)pH0h);

    // layer 1 (commuted): G1' = M * (H0@W1); H1 = relu(spmm64(adjZ, G1')*AM + b1)
    gemm_f16_kernel<128, 64, 2, 3><<<gemmBlocks, 256>>>((const __half*)pH0h, W1, M, (__half*)pG1h);
    spmm64_kernel<<<spmmBlocks, 256>>>((const __half*)pG1h, AM, b1, (__half*)pAh);   // Ah := H1

    // layer 2 (commuted): G2 = H1@W2; out = log_softmax(spmm40(adj, G2) + b2)
    gemm_f16_kernel<64, 40, 1, 2><<<gemmBlocks, 256>>>((const __half*)pAh, W2, nullptr, (__half*)pG2h);
    spmm40_final_kernel<<<spmmBlocks, 256>>>((const __half*)pG2h, b2, out);
}

// round 17
// speedup vs baseline: 1.4895x; 1.1659x over previous
#include <cuda_runtime.h>
#include <cuda_fp16.h>
#include <math.h>

#define NN 50000
#define EE 800000
#define NF 128
#define NH 64
#define NC 40

// ---- scratch (static device globals; no allocation in kernel_launch) ----
__device__ __half  g_xh[NN * NF];    // fp16 copy of M*x
__device__ __half  g_Ah[NN * NF];    // spmm0 out (AM folded); later reused as H1 (NN x 64)
__device__ __half  g_H0h[NN * NF];   // relu(A@W0+b0)
__device__ __half  g_G1h[NN * NH];   // M * (H0@W1)  (gathered by spmm64)
__device__ __half  g_G2h[NN * NC];   // H1@W2        (gathered by spmm40)
__device__ int     g_hist[NN];
__device__ int     g_rowptr[NN + 1];
__device__ int     g_cursor[NN];
__device__ __align__(16) uint2 g_e8[EE];   // {col_u16 | v_f16<<16,  half2(adjZ,adjZ)}

// ---------------- combo: hist (atomic) + (M*x)->fp16 convert, one launch ----------------
#define HIST_BLOCKS ((EE + 255) / 256)
#define CVT_BLOCKS  ((NN * NF / 2 + 255) / 256)
__global__ void hist_tohalf_kernel(const int* __restrict__ row, const float* __restrict__ x,
                                   const float* __restrict__ M) {
    int b = blockIdx.x;
    if (b < HIST_BLOCKS) {
        int e = b * 256 + threadIdx.x;
        if (e < EE) atomicAdd(&g_hist[row[e]], 1);
    } else {
        int i = (b - HIST_BLOCKS) * 256 + threadIdx.x;
        if (i < NN * NF / 2) {
            float2 v = ((const float2*)x)[i];
            float m = __ldg(&M[i >> 6]);          // 64 float2 per node row
            ((__half2*)g_xh)[i] = __float22half2_rn(make_float2(v.x * m, v.y * m));
        }
    }
}

// ---------------- single-block exclusive scan ----------------
__global__ void scan_kernel() {
    __shared__ int ssum[1024];
    const int CH = (NN + 1023) / 1024;   // 49
    int t = threadIdx.x;
    int base = t * CH;
    int local = 0;
    for (int i = 0; i < CH; i++) {
        int idx = base + i;
        if (idx < NN) local += g_hist[idx];
    }
    ssum[t] = local;
    __syncthreads();
    for (int off = 1; off < 1024; off <<= 1) {
        int v = (t >= off) ? ssum[t - off] : 0;
        __syncthreads();
        ssum[t] += v;
        __syncthreads();
    }
    int run = ssum[t] - local;
    for (int i = 0; i < CH; i++) {
        int idx = base + i;
        if (idx < NN) {
            g_rowptr[idx] = run;
            g_cursor[idx] = run;
            run += g_hist[idx];
        }
    }
    if (t == 0) g_rowptr[NN] = EE;
}

// ---- scatter: 2 edges/thread for MLP; weight stored as half2(adjZ,adjZ) ----
__global__ void scatter_kernel(const int* __restrict__ row, const int* __restrict__ col,
                               const float* __restrict__ adj, const float* __restrict__ adjZ) {
    const int HALF = EE / 2;
    int t = blockIdx.x * blockDim.x + threadIdx.x;
    if (t >= HALF) return;
    int e0 = t, e1 = t + HALF;
    int c0 = col[e0], c1 = col[e1];
    int r0 = row[e0], r1 = row[e1];
    float a0 = adj[e0], a1 = adj[e1];
    float z0 = adjZ[e0], z1 = adjZ[e1];
    int p0 = atomicAdd(&g_cursor[r0], 1);
    int p1 = atomicAdd(&g_cursor[r1], 1);
    unsigned lo0 = (unsigned)(unsigned short)c0 |
                   ((unsigned)__half_as_ushort(__float2half_rn(a0)) << 16);
    unsigned lo1 = (unsigned)(unsigned short)c1 |
                   ((unsigned)__half_as_ushort(__float2half_rn(a1)) << 16);
    __half2 z20 = __half2half2(__float2half_rn(z0));
    __half2 z21 = __half2half2(__float2half_rn(z1));
    g_e8[p0] = make_uint2(lo0, *(unsigned*)&z20);
    g_e8[p1] = make_uint2(lo1, *(unsigned*)&z21);
}

__device__ __forceinline__ __half2 u2h2(unsigned u) { return *(__half2*)&u; }

// ---------------- SPMM 128-feat (layer 0): uint4 edge loads, 4-chain HFMA2, flush/8 ----------------
__global__ void spmm128h_kernel(const __half* __restrict__ Xh, const float* __restrict__ AM,
                                __half* __restrict__ out) {
    int r = (blockIdx.x * blockDim.x + threadIdx.x) >> 5;
    if (r >= NN) return;
    int lane = threadIdx.x & 31;
    int s = g_rowptr[r];
    int e = g_rowptr[r + 1];
    const uint2* X = (const uint2*)Xh;

    float4 acc = make_float4(0.f, 0.f, 0.f, 0.f);
    const __half2 hz = __float2half2_rn(0.f);
    int i = s;
    // peel to even index so uint4 loads are 16B-aligned
    if ((i & 1) && i < e) {
        uint2 e0 = __ldg(&g_e8[i]);
        uint2 u0 = __ldg(&X[(e0.x & 0xFFFFu) * 32 + lane]);
        float w = __low2float(u2h2(e0.y));
        float2 a = __half22float2(u2h2(u0.x));
        float2 b = __half22float2(u2h2(u0.y));
        acc.x += w * a.x; acc.y += w * a.y; acc.z += w * b.x; acc.w += w * b.y;
        i++;
    }
#pragma unroll 1
    for (; i + 8 <= e; i += 8) {
        uint4 p0 = __ldg((const uint4*)&g_e8[i]);       // edges i, i+1
        uint4 p1 = __ldg((const uint4*)&g_e8[i + 2]);
        uint4 p2 = __ldg((const uint4*)&g_e8[i + 4]);
        uint4 p3 = __ldg((const uint4*)&g_e8[i + 6]);
        uint2 u0 = __ldg(&X[(p0.x & 0xFFFFu) * 32 + lane]);
        uint2 u1 = __ldg(&X[(p0.z & 0xFFFFu) * 32 + lane]);
        uint2 u2 = __ldg(&X[(p1.x & 0xFFFFu) * 32 + lane]);
        uint2 u3 = __ldg(&X[(p1.z & 0xFFFFu) * 32 + lane]);
        uint2 u4 = __ldg(&X[(p2.x & 0xFFFFu) * 32 + lane]);
        uint2 u5 = __ldg(&X[(p2.z & 0xFFFFu) * 32 + lane]);
        uint2 u6 = __ldg(&X[(p3.x & 0xFFFFu) * 32 + lane]);
        uint2 u7 = __ldg(&X[(p3.z & 0xFFFFu) * 32 + lane]);
        // 4 independent chain pairs, each 2 HFMA2 deep
        __half2 a0 = __hfma2(u2h2(p0.y), u2h2(u0.x), hz), b0 = __hfma2(u2h2(p0.y), u2h2(u0.y), hz);
        __half2 a1 = __hfma2(u2h2(p0.w), u2h2(u1.x), hz), b1 = __hfma2(u2h2(p0.w), u2h2(u1.y), hz);
        __half2 a2 = __hfma2(u2h2(p1.y), u2h2(u2.x), hz), b2 = __hfma2(u2h2(p1.y), u2h2(u2.y), hz);
        __half2 a3 = __hfma2(u2h2(p1.w), u2h2(u3.x), hz), b3 = __hfma2(u2h2(p1.w), u2h2(u3.y), hz);
        a0 = __hfma2(u2h2(p2.y), u2h2(u4.x), a0); b0 = __hfma2(u2h2(p2.y), u2h2(u4.y), b0);
        a1 = __hfma2(u2h2(p2.w), u2h2(u5.x), a1); b1 = __hfma2(u2h2(p2.w), u2h2(u5.y), b1);
        a2 = __hfma2(u2h2(p3.y), u2h2(u6.x), a2); b2 = __hfma2(u2h2(p3.y), u2h2(u6.y), b2);
        a3 = __hfma2(u2h2(p3.w), u2h2(u7.x), a3); b3 = __hfma2(u2h2(p3.w), u2h2(u7.y), b3);
        // flush to fp32
        __half2 sa = __hadd2(__hadd2(a0, a1), __hadd2(a2, a3));
        __half2 sb = __hadd2(__hadd2(b0, b1), __hadd2(b2, b3));
        float2 fa = __half22float2(sa);
        float2 fb = __half22float2(sb);
        acc.x += fa.x; acc.y += fa.y; acc.z += fb.x; acc.w += fb.y;
    }
    for (; i < e; i++) {
        uint2 e0 = __ldg(&g_e8[i]);
        uint2 u0 = __ldg(&X[(e0.x & 0xFFFFu) * 32 + lane]);
        float w = __low2float(u2h2(e0.y));
        float2 a = __half22float2(u2h2(u0.x));
        float2 b = __half22float2(u2h2(u0.y));
        acc.x += w * a.x; acc.y += w * a.y; acc.z += w * b.x; acc.w += w * b.y;
    }
    float am = __ldg(&AM[r]);
    __half2 h0 = __float22half2_rn(make_float2(acc.x * am, acc.y * am));
    __half2 h1 = __float22half2_rn(make_float2(acc.z * am, acc.w * am));
    ((uint2*)out)[r * 32 + lane] = make_uint2(*(unsigned*)&h0, *(unsigned*)&h1);
}

// ---------------- ldmatrix helpers ----------------
__device__ __forceinline__ void ldsm_x4(unsigned& r0, unsigned& r1, unsigned& r2, unsigned& r3,
                                        unsigned addr) {
    asm volatile("ldmatrix.sync.aligned.m8n8.x4.shared.b16 {%0,%1,%2,%3}, [%4];"
                 : "=r"(r0), "=r"(r1), "=r"(r2), "=r"(r3) : "r"(addr));
}
__device__ __forceinline__ void ldsm_x2_trans(unsigned& r0, unsigned& r1, unsigned addr) {
    asm volatile("ldmatrix.sync.aligned.m8n8.x2.trans.shared.b16 {%0,%1}, [%2];"
                 : "=r"(r0), "=r"(r1) : "r"(addr));
}

// ---------------- fp16 tensor-core GEMM (mma.sync m16n8k16, fp32 accum) ----------------
// EPI 1: bias+relu fp16 out; EPI 2: plain fp16 out; EPI 3: row-scale by aux[r], fp16 out.
template <int KIN, int NOUT, int WARPN, int EPI>
__global__ __launch_bounds__(256) void gemm_f16_kernel(
        const __half* __restrict__ A, const float* __restrict__ W,
        const float* __restrict__ aux, __half* __restrict__ out) {
    constexpr int BM  = 128;
    constexpr int BK  = 16;
    constexpr int AS  = 24;
    constexpr int WS  = (NOUT == 40) ? 56 : NOUT + 8;
    constexpr int NMW = 8 / WARPN;
    constexpr int MF  = BM / (16 * NMW);
    constexpr int WN  = NOUT / WARPN;
    constexpr int NFR = WN / 8;

    __shared__ __align__(16) __half As[BM * AS];
    __shared__ __align__(16) __half Ws[BK * WS];   // row-major [k][n]
    __shared__ float biass[NOUT];

    int tid    = threadIdx.x;
    int lane   = tid & 31;
    int wid    = tid >> 5;
    int warp_m = wid % NMW;
    int warp_n = wid / NMW;
    int br     = blockIdx.x * BM;
    int qr     = lane >> 2;
    int qc     = lane & 3;

    if (EPI == 1 && tid < NOUT) biass[tid] = aux[tid];

    unsigned as_base = (unsigned)__cvta_generic_to_shared(As);
    unsigned ws_base = (unsigned)__cvta_generic_to_shared(Ws);
    int a_row  = (lane & 15);
    int a_colh = (lane >> 4) << 3;
    int b_row  = (lane & 15);

    float acc[MF][NFR][4];
#pragma unroll
    for (int i = 0; i < MF; i++)
#pragma unroll
        for (int j = 0; j < NFR; j++)
#pragma unroll
            for (int k = 0; k < 4; k++) acc[i][j][k] = 0.f;

    for (int kk = 0; kk < KIN; kk += BK) {
#pragma unroll
        for (int it = 0; it < 2; it++) {
            int i  = tid + it * 256;
            int m  = i >> 2;
            int c4 = (i & 3) * 4;
            int gr = br + m;
            uint2 v = make_uint2(0u, 0u);
            if (gr < NN) v = *(const uint2*)&A[gr * KIN + kk + c4];
            *(uint2*)&As[m * AS + c4] = v;
        }
#pragma unroll
        for (int i = tid; i < BK * NOUT / 4; i += 256) {
            int k  = i / (NOUT / 4);
            int n4 = (i % (NOUT / 4)) * 4;
            float4 v = *(const float4*)&W[(kk + k) * NOUT + n4];
            __half2 h0 = __float22half2_rn(make_float2(v.x, v.y));
            __half2 h1 = __float22half2_rn(make_float2(v.z, v.w));
            *(uint2*)&Ws[k * WS + n4] = make_uint2(*(unsigned*)&h0, *(unsigned*)&h1);
        }
        __syncthreads();

        unsigned b[NFR][2];
#pragma unroll
        for (int nf = 0; nf < NFR; nf++) {
            int n0 = warp_n * WN + nf * 8;
            ldsm_x2_trans(b[nf][0], b[nf][1],
                          ws_base + (unsigned)((b_row * WS + n0) * 2));
        }
#pragma unroll
        for (int mf = 0; mf < MF; mf++) {
            int m0 = warp_m * (16 * MF) + mf * 16;
            unsigned a0, a1, a2, a3;
            ldsm_x4(a0, a1, a2, a3,
                    as_base + (unsigned)(((m0 + a_row) * AS + a_colh) * 2));
#pragma unroll
            for (int nf = 0; nf < NFR; nf++) {
                asm("mma.sync.aligned.m16n8k16.row.col.f32.f16.f16.f32 "
                    "{%0,%1,%2,%3}, {%4,%5,%6,%7}, {%8,%9}, {%0,%1,%2,%3};"
                    : "+f"(acc[mf][nf][0]), "+f"(acc[mf][nf][1]),
                      "+f"(acc[mf][nf][2]), "+f"(acc[mf][nf][3])
                    : "r"(a0), "r"(a1), "r"(a2), "r"(a3),
                      "r"(b[nf][0]), "r"(b[nf][1]));
            }
        }
        __syncthreads();
    }

#pragma unroll
    for (int mf = 0; mf < MF; mf++) {
        int r0 = br + warp_m * (16 * MF) + mf * 16 + qr;
        int r1 = r0 + 8;
        float s0 = 1.f, s1 = 1.f;
        if (EPI == 3) {
            if (r0 < NN) s0 = __ldg(&aux[r0]);
            if (r1 < NN) s1 = __ldg(&aux[r1]);
        }
#pragma unroll
        for (int nf = 0; nf < NFR; nf++) {
            int c = warp_n * WN + nf * 8 + 2 * qc;
            float v0 = acc[mf][nf][0], v1 = acc[mf][nf][1];
            float v2 = acc[mf][nf][2], v3 = acc[mf][nf][3];
            if (EPI == 1) {
                float bx = biass[c], by = biass[c + 1];
                v0 = fmaxf(v0 + bx, 0.f); v1 = fmaxf(v1 + by, 0.f);
                v2 = fmaxf(v2 + bx, 0.f); v3 = fmaxf(v3 + by, 0.f);
            } else if (EPI == 3) {
                v0 *= s0; v1 *= s0; v2 *= s1; v3 *= s1;
            }
            if (r0 < NN) *(__half2*)&out[r0 * NOUT + c] = __float22half2_rn(make_float2(v0, v1));
            if (r1 < NN) *(__half2*)&out[r1 * NOUT + c] = __float22half2_rn(make_float2(v2, v3));
        }
    }
}

// ---- layer 1 spmm: H1 = relu(spmm64(adjZ, G1')*AM + b1), uint4 edges + HFMA2 ----
__global__ void spmm64_kernel(const __half* __restrict__ G1h, const float* __restrict__ AM,
                              const float* __restrict__ b1, __half* __restrict__ H1h) {
    int tid = threadIdx.x;
    int r = blockIdx.x * (blockDim.x >> 5) + (tid >> 5);
    if (r >= NN) return;
    int lane = tid & 31;
    int s = g_rowptr[r];
    int e = g_rowptr[r + 1];
    const __half2* X = (const __half2*)G1h;   // 32 half2 per row

    float2 acc = make_float2(0.f, 0.f);
    const __half2 hz = __float2half2_rn(0.f);
    int i = s;
    if ((i & 1) && i < e) {
        uint2 e0 = __ldg(&g_e8[i]);
        float2 x0 = __half22float2(__ldg(&X[(e0.x & 0xFFFFu) * 32 + lane]));
        float w = __low2float(u2h2(e0.y));
        acc.x += w * x0.x; acc.y += w * x0.y;
        i++;
    }
#pragma unroll 1
    for (; i + 8 <= e; i += 8) {
        uint4 p0 = __ldg((const uint4*)&g_e8[i]);
        uint4 p1 = __ldg((const uint4*)&g_e8[i + 2]);
        uint4 p2 = __ldg((const uint4*)&g_e8[i + 4]);
        uint4 p3 = __ldg((const uint4*)&g_e8[i + 6]);
        __half2 x0 = __ldg(&X[(p0.x & 0xFFFFu) * 32 + lane]);
        __half2 x1 = __ldg(&X[(p0.z & 0xFFFFu) * 32 + lane]);
        __half2 x2 = __ldg(&X[(p1.x & 0xFFFFu) * 32 + lane]);
        __half2 x3 = __ldg(&X[(p1.z & 0xFFFFu) * 32 + lane]);
        __half2 x4 = __ldg(&X[(p2.x & 0xFFFFu) * 32 + lane]);
        __half2 x5 = __ldg(&X[(p2.z & 0xFFFFu) * 32 + lane]);
        __half2 x6 = __ldg(&X[(p3.x & 0xFFFFu) * 32 + lane]);
        __half2 x7 = __ldg(&X[(p3.z & 0xFFFFu) * 32 + lane]);
        __half2 a0 = __hfma2(u2h2(p0.y), x0, hz);
        __half2 a1 = __hfma2(u2h2(p0.w), x1, hz);
        __half2 a2 = __hfma2(u2h2(p1.y), x2, hz);
        __half2 a3 = __hfma2(u2h2(p1.w), x3, hz);
        a0 = __hfma2(u2h2(p2.y), x4, a0);
        a1 = __hfma2(u2h2(p2.w), x5, a1);
        a2 = __hfma2(u2h2(p3.y), x6, a2);
        a3 = __hfma2(u2h2(p3.w), x7, a3);
        float2 f = __half22float2(__hadd2(__hadd2(a0, a1), __hadd2(a2, a3)));
        acc.x += f.x; acc.y += f.y;
    }
    for (; i < e; i++) {
        uint2 e0 = __ldg(&g_e8[i]);
        float2 x0 = __half22float2(__ldg(&X[(e0.x & 0xFFFFu) * 32 + lane]));
        float w = __low2float(u2h2(e0.y));
        acc.x += w * x0.x; acc.y += w * x0.y;
    }

    float am = __ldg(&AM[r]);
    float2 b = __ldg(&((const float2*)b1)[lane]);
    float2 hv;
    hv.x = fmaxf(acc.x * am + b.x, 0.f);
    hv.y = fmaxf(acc.y * am + b.y, 0.f);
    ((__half2*)H1h)[r * 32 + lane] = __float22half2_rn(hv);
}

// ---- layer 2 fused: out = log_softmax(spmm40(v, G2h) + b2), uint4 edges + HFMA2 ----
__global__ void spmm40_final_kernel(const __half* __restrict__ G2h, const float* __restrict__ b2,
                                    float* __restrict__ out) {
    int tid = threadIdx.x;
    int r = blockIdx.x * (blockDim.x >> 5) + (tid >> 5);
    if (r >= NN) return;
    int lane = tid & 31;
    bool act = lane < 20;
    int s = g_rowptr[r];
    int e = g_rowptr[r + 1];
    const __half2* X = (const __half2*)G2h;
    int li = act ? lane : 0;

    float2 acc = make_float2(0.f, 0.f);
    const __half2 hz = __float2half2_rn(0.f);
    int i = s;
    if ((i & 1) && i < e) {
        uint2 e0 = __ldg(&g_e8[i]);
        float2 x0 = __half22float2(__ldg(&X[(e0.x & 0xFFFFu) * 20 + li]));
        float w = __half2float(__ushort_as_half((unsigned short)(e0.x >> 16)));
        acc.x += w * x0.x; acc.y += w * x0.y;
        i++;
    }
#pragma unroll 1
    for (; i + 8 <= e; i += 8) {
        uint4 p0 = __ldg((const uint4*)&g_e8[i]);
        uint4 p1 = __ldg((const uint4*)&g_e8[i + 2]);
        uint4 p2 = __ldg((const uint4*)&g_e8[i + 4]);
        uint4 p3 = __ldg((const uint4*)&g_e8[i + 6]);
        __half2 x0 = __ldg(&X[(p0.x & 0xFFFFu) * 20 + li]);
        __half2 x1 = __ldg(&X[(p0.z & 0xFFFFu) * 20 + li]);
        __half2 x2 = __ldg(&X[(p1.x & 0xFFFFu) * 20 + li]);
        __half2 x3 = __ldg(&X[(p1.z & 0xFFFFu) * 20 + li]);
        __half2 x4 = __ldg(&X[(p2.x & 0xFFFFu) * 20 + li]);
        __half2 x5 = __ldg(&X[(p2.z & 0xFFFFu) * 20 + li]);
        __half2 x6 = __ldg(&X[(p3.x & 0xFFFFu) * 20 + li]);
        __half2 x7 = __ldg(&X[(p3.z & 0xFFFFu) * 20 + li]);
        __half2 v0 = __half2half2(__ushort_as_half((unsigned short)(p0.x >> 16)));
        __half2 v1 = __half2half2(__ushort_as_half((unsigned short)(p0.z >> 16)));
        __half2 v2 = __half2half2(__ushort_as_half((unsigned short)(p1.x >> 16)));
        __half2 v3 = __half2half2(__ushort_as_half((unsigned short)(p1.z >> 16)));
        __half2 v4 = __half2half2(__ushort_as_half((unsigned short)(p2.x >> 16)));
        __half2 v5 = __half2half2(__ushort_as_half((unsigned short)(p2.z >> 16)));
        __half2 v6 = __half2half2(__ushort_as_half((unsigned short)(p3.x >> 16)));
        __half2 v7 = __half2half2(__ushort_as_half((unsigned short)(p3.z >> 16)));
        __half2 a0 = __hfma2(v0, x0, hz);
        __half2 a1 = __hfma2(v1, x1, hz);
        __half2 a2 = __hfma2(v2, x2, hz);
        __half2 a3 = __hfma2(v3, x3, hz);
        a0 = __hfma2(v4, x4, a0);
        a1 = __hfma2(v5, x5, a1);
        a2 = __hfma2(v6, x6, a2);
        a3 = __hfma2(v7, x7, a3);
        float2 f = __half22float2(__hadd2(__hadd2(a0, a1), __hadd2(a2, a3)));
        acc.x += f.x; acc.y += f.y;
    }
    for (; i < e; i++) {
        uint2 e0 = __ldg(&g_e8[i]);
        float2 x0 = __half22float2(__ldg(&X[(e0.x & 0xFFFFu) * 20 + li]));
        float w = __half2float(__ushort_as_half((unsigned short)(e0.x >> 16)));
        acc.x += w * x0.x; acc.y += w * x0.y;
    }

    float v0 = 0.f, v1 = 0.f;
    if (act) {
        float2 b = __ldg(&((const float2*)b2)[lane]);
        v0 = acc.x + b.x;
        v1 = acc.y + b.y;
    }

    float m = act ? fmaxf(v0, v1) : -INFINITY;
#pragma unroll
    for (int o = 16; o > 0; o >>= 1) m = fmaxf(m, __shfl_xor_sync(0xffffffffu, m, o));
    float sum = act ? (__expf(v0 - m) + __expf(v1 - m)) : 0.f;
#pragma unroll
    for (int o = 16; o > 0; o >>= 1) sum += __shfl_xor_sync(0xffffffffu, sum, o);
    float lse = m + __logf(sum);

    if (act) {
        ((float2*)out)[r * 20 + lane] = make_float2(v0 - lse, v1 - lse);
    }
}

// ---------------- launch ----------------
extern "C" void kernel_launch(void* const* d_in, const int* in_sizes, int n_in,
                              void* d_out, int out_size) {
    const float* x    = (const float*)d_in[0];
    const float* M    = (const float*)d_in[1];
    const float* AM   = (const float*)d_in[2];
    const float* adj  = (const float*)d_in[3];
    const float* adjZ = (const float*)d_in[4];
    const float* W0   = (const float*)d_in[5];
    const float* b0   = (const float*)d_in[6];
    const float* W1   = (const float*)d_in[7];
    const float* b1   = (const float*)d_in[8];
    const float* W2   = (const float*)d_in[9];
    const float* b2   = (const float*)d_in[10];
    const int*   row  = (const int*)d_in[11];
    const int*   col  = (const int*)d_in[12];
    float* out = (float*)d_out;

    void *pXh, *pAh, *pH0h, *pG1h, *pG2h, *pHist;
    cudaGetSymbolAddress(&pXh,  g_xh);
    cudaGetSymbolAddress(&pAh,  g_Ah);
    cudaGetSymbolAddress(&pH0h, g_H0h);
    cudaGetSymbolAddress(&pG1h, g_G1h);
    cudaGetSymbolAddress(&pG2h, g_G2h);
    cudaGetSymbolAddress(&pHist, g_hist);

    // CSR build + (M*x)->fp16 conversion
    cudaMemsetAsync(pHist, 0, NN * sizeof(int));
    hist_tohalf_kernel<<<HIST_BLOCKS + CVT_BLOCKS, 256>>>(row, x, M);
    scan_kernel<<<1, 1024>>>();
    scatter_kernel<<<(EE / 2 + 255) / 256, 256>>>(row, col, adj, adjZ);

    const int spmmBlocks = (NN + 7) / 8;        // 8 warps/block, 1 warp/row
    const int gemmBlocks = (NN + 127) / 128;    // BM=128

    // layer 0: H0 = relu((spmm(adjZ, M*x) * AM) @ W0 + b0)
    spmm128h_kernel<<<spmmBlocks, 256>>>((const __half*)pXh, AM, (__half*)pAh);
    gemm_f16_kernel<128, 128, 2, 1><<<gemmBlocks, 256>>>((const __half*)pAh, W0, b0, (__half*)pH0h);

    // layer 1 (commuted): G1' = M * (H0@W1); H1 = relu(spmm64(adjZ, G1')*AM + b1)
    gemm_f16_kernel<128, 64, 2, 3><<<gemmBlocks, 256>>>((const __half*)pH0h, W1, M, (__half*)pG1h);
    spmm64_kernel<<<spmmBlocks, 256>>>((const __half*)pG1h, AM, b1, (__half*)pAh);   // Ah := H1

    // layer 2 (commuted): G2 = H1@W2; out = log_softmax(spmm40(adj, G2) + b2)
    gemm_f16_kernel<64, 40, 1, 2><<<gemmBlocks, 256>>>((const __half*)pAh, W2, nullptr, (__half*)pG2h);
    spmm40_final_kernel<<<spmmBlocks, 256>>>((const __half*)pG2h, b2, out);
}